// round 13
// baseline (speedup 1.0000x reference)
#include <cuda_runtime.h>

// Scratch (no device allocations allowed) — reset by the last block each run,
// so every kernel_launch invocation is deterministic.
static __device__ double   g_acc   = 0.0;
static __device__ unsigned g_count = 0;

// Math (per row, K=16):
//   row = lse(w + comp) - lse(w) = log(S2) - log(S1)   (unshifted; inputs bounded)
//   S1 = sum_k e^{w_k}
//   S2 = sum_k e^{w_k} * e^{m_k} * (1/s_k) / (1 + e^{m_k})^2 ,  m = -|z|
//
// Layout: 4 lanes cooperate on one row; each lane one float4 per tensor ->
// warp reads 512B fully-dense per LDG.128 (4 cache lines, no waste).
//
// Launch: GB300 has 152 SMs (not 148 — that's B300-SXM). grid = 152 x 8 =
// 1216 -> exactly ONE perfectly-balanced wave (regs<=32 keeps 8 blocks/SM
// resident). Previous 1184-grid left a 2.7% block-count imbalance across SMs.
__global__ __launch_bounds__(256) void MixtureOfLogistics_kernel(
    const float* __restrict__ weight,
    const float* __restrict__ loc,
    const float* __restrict__ scale,
    const float* __restrict__ targets,
    float* __restrict__ out,
    int n_rows, double inv_n)
{
    const int tid   = blockIdx.x * blockDim.x + threadIdx.x;
    const int lane4 = tid & 3;
    const int group = tid >> 2;
    const int n_grp = (gridDim.x * blockDim.x) >> 2;

    float acc = 0.0f;

    for (int row = group; row < n_rows; row += n_grp) {
        const float t = __ldg(targets + row);
        const size_t base = (size_t)row * 16 + (size_t)lane4 * 4;

        const float4 w4 = *reinterpret_cast<const float4*>(weight + base);
        const float4 l4 = *reinterpret_cast<const float4*>(loc    + base);
        const float4 s4 = *reinterpret_cast<const float4*>(scale  + base);

        const float w[4] = {w4.x, w4.y, w4.z, w4.w};
        const float l[4] = {l4.x, l4.y, l4.z, l4.w};
        const float s[4] = {s4.x, s4.y, s4.z, s4.w};

        float S1 = 0.0f, S2 = 0.0f;
        #pragma unroll
        for (int c = 0; c < 4; c++) {
            float rs = __fdividef(1.0f, s[c]);      // MUFU rcp
            float m  = -fabsf((t - l[c]) * rs);
            float e  = __expf(m);                   // MUFU ex2
            float ew = __expf(w[c]);                // MUFU ex2 (shared S1/S2)
            float rd = __fdividef(1.0f, 1.0f + e);  // MUFU rcp
            S1 += ew;
            S2 += ew * e * rs * (rd * rd);
        }

        // 4-lane group reductions (2 shuffle steps each).
        S1 += __shfl_xor_sync(0xffffffffu, S1, 1);
        S1 += __shfl_xor_sync(0xffffffffu, S1, 2);
        S2 += __shfl_xor_sync(0xffffffffu, S2, 1);
        S2 += __shfl_xor_sync(0xffffffffu, S2, 2);

        if (lane4 == 0) {
            S2 = fmaxf(S2, 1e-37f);                 // underflow guard
            acc += __logf(__fdividef(S2, S1));      // log(S2) - log(S1)
        }
    }

    // Warp reduction (only lane4==0 lanes hold nonzero partials).
    #pragma unroll
    for (int off = 16; off > 0; off >>= 1)
        acc += __shfl_xor_sync(0xffffffffu, acc, off);

    __shared__ float warp_part[8];
    const int warp = threadIdx.x >> 5;
    const int lane = threadIdx.x & 31;
    if (lane == 0) warp_part[warp] = acc;
    __syncthreads();

    if (warp == 0) {
        float v = (lane < (int)(blockDim.x >> 5)) ? warp_part[lane] : 0.0f;
        #pragma unroll
        for (int off = 4; off > 0; off >>= 1)
            v += __shfl_xor_sync(0xffffffffu, v, off);

        if (lane == 0) {
            atomicAdd(&g_acc, (double)v);
            __threadfence();
            unsigned done = atomicAdd(&g_count, 1u);
            if (done == gridDim.x - 1) {
                out[0] = (float)(g_acc * inv_n);
                g_acc   = 0.0;     // reset for next deterministic replay
                g_count = 0u;
                __threadfence();
            }
        }
    }
}

extern "C" void kernel_launch(void* const* d_in, const int* in_sizes, int n_in,
                              void* d_out, int out_size) {
    const float* weight  = (const float*)d_in[0];
    const float* loc     = (const float*)d_in[1];
    const float* scale   = (const float*)d_in[2];
    const float* targets = (const float*)d_in[3];
    float* out = (float*)d_out;

    const int n_rows = in_sizes[3];          // B*T = 2,097,152
    const double inv_n = 1.0 / (double)n_rows;

    // One balanced wave on GB300: 152 SMs x 8 blocks/SM (regs<=32, 256 thr).
    MixtureOfLogistics_kernel<<<1216, 256>>>(weight, loc, scale, targets, out,
                                             n_rows, inv_n);
}